// round 2
// baseline (speedup 1.0000x reference)
#include <cuda_runtime.h>
#include <cuda_bf16.h>

#define BATCH 8
#define SEQ   512
#define HID   1024
#define NHEAD 16
#define HD    64
#define MROWS (BATCH*SEQ)

__device__ float g_q[BATCH*NHEAD*SEQ*HD];
__device__ float g_k[BATCH*NHEAD*SEQ*HD];
__device__ float g_v[BATCH*NHEAD*SEQ*HD];
__device__ float g_attn[BATCH*SEQ*HID];

#define BM 128
#define BN 128
#define BK 8

__global__ __launch_bounds__(256)
void sgemm_nt(const float* __restrict__ A, const float* __restrict__ W,
              const float* __restrict__ bias, float* __restrict__ Cout,
              int K, float scale, int dst)
{
    if (A == nullptr) A = g_attn;

    __shared__ float As[BK][BM];
    __shared__ float Bs[BK][BN];

    const int bm = blockIdx.y * BM;
    const int bn = blockIdx.x * BN;
    const int tid = threadIdx.x;
    const int tm = tid >> 4;
    const int tn = tid & 15;
    const int lr = tid >> 1;
    const int lc = (tid & 1) * 4;

    float acc[8][8];
    #pragma unroll
    for (int i = 0; i < 8; i++)
        #pragma unroll
        for (int j = 0; j < 8; j++) acc[i][j] = 0.f;

    const float* Aptr = A + (long)(bm + lr) * K + lc;
    const float* Wptr = W + (long)(bn + lr) * K + lc;

    for (int k0 = 0; k0 < K; k0 += BK) {
        float4 a4 = *(const float4*)(Aptr + k0);
        float4 b4 = *(const float4*)(Wptr + k0);
        __syncthreads();
        As[lc+0][lr] = a4.x; As[lc+1][lr] = a4.y;
        As[lc+2][lr] = a4.z; As[lc+3][lr] = a4.w;
        Bs[lc+0][lr] = b4.x; Bs[lc+1][lr] = b4.y;
        Bs[lc+2][lr] = b4.z; Bs[lc+3][lr] = b4.w;
        __syncthreads();

        #pragma unroll
        for (int kk = 0; kk < BK; kk++) {
            float af[8], bf[8];
            #pragma unroll
            for (int i = 0; i < 8; i++) af[i] = As[kk][tm*8 + i];
            #pragma unroll
            for (int j = 0; j < 8; j++) bf[j] = Bs[kk][tn*8 + j];
            #pragma unroll
            for (int i = 0; i < 8; i++)
                #pragma unroll
                for (int j = 0; j < 8; j++)
                    acc[i][j] += af[i] * bf[j];
        }
    }

    float* C;
    if      (dst == 0) C = g_q;
    else if (dst == 1) C = g_k;
    else if (dst == 2) C = g_v;
    else               C = Cout;

    #pragma unroll
    for (int i = 0; i < 8; i++) {
        const int m = bm + tm*8 + i;
        #pragma unroll
        for (int j = 0; j < 8; j++) {
            const int n = bn + tn*8 + j;
            float v = (acc[i][j] + bias[n]) * scale;
            if (dst < 3) {
                const int b = m >> 9, s = m & 511;
                const int h = n >> 6, d = n & 63;
                C[(((long)(b*NHEAD + h))*SEQ + s)*HD + d] = v;
            } else {
                C[(long)m * HID + n] = v;
            }
        }
    }
}

#define QT 64
#define SMEM_ATTN ((QT*SEQ + 2*QT*65) * (int)sizeof(float))

__global__ __launch_bounds__(256)
void attn_kernel(const float* __restrict__ mask, const float* __restrict__ kg,
                 const int* __restrict__ lena, const float* __restrict__ hy,
                 const int* __restrict__ layer_p)
{
    extern __shared__ float sm[];
    float* sc = sm;
    float* Qs = sm + QT*SEQ;
    float* Ks = Qs + QT*65;

    const int tid = threadIdx.x;
    const int bh = blockIdx.x;
    const int b = bh >> 4, h = bh & 15;
    const int q0 = blockIdx.y * QT;

    const long head_off = ((long)(b*NHEAD + h)) * SEQ * HD;
    const float* qbase = g_q + head_off + (long)q0 * HD;

    for (int i = tid; i < QT*16; i += 256) {
        const int r = i >> 4, c = (i & 15) * 4;
        float4 v = *(const float4*)(qbase + r*HD + c);
        Qs[r*65 + c+0] = v.x; Qs[r*65 + c+1] = v.y;
        Qs[r*65 + c+2] = v.z; Qs[r*65 + c+3] = v.w;
    }

    const int tx = tid & 15, ty = tid >> 4;

    for (int kt = 0; kt < SEQ/QT; kt++) {
        const float* kbase = g_k + head_off + (long)(kt*QT) * HD;
        __syncthreads();
        for (int i = tid; i < QT*16; i += 256) {
            const int r = i >> 4, c = (i & 15) * 4;
            float4 v = *(const float4*)(kbase + r*HD + c);
            Ks[r*65 + c+0] = v.x; Ks[r*65 + c+1] = v.y;
            Ks[r*65 + c+2] = v.z; Ks[r*65 + c+3] = v.w;
        }
        __syncthreads();

        float acc[4][4];
        #pragma unroll
        for (int i = 0; i < 4; i++)
            #pragma unroll
            for (int j = 0; j < 4; j++) acc[i][j] = 0.f;

        #pragma unroll 8
        for (int d = 0; d < HD; d++) {
            float qv[4], kv[4];
            #pragma unroll
            for (int i = 0; i < 4; i++) qv[i] = Qs[(ty*4+i)*65 + d];
            #pragma unroll
            for (int j = 0; j < 4; j++) kv[j] = Ks[(tx*4+j)*65 + d];
            #pragma unroll
            for (int i = 0; i < 4; i++)
                #pragma unroll
                for (int j = 0; j < 4; j++)
                    acc[i][j] += qv[i] * kv[j];
        }

        #pragma unroll
        for (int i = 0; i < 4; i++) {
            const int r = ty*4 + i;
            const long mrow = ((long)b*SEQ + (q0 + r)) * SEQ;
            #pragma unroll
            for (int j = 0; j < 4; j++) {
                const int c = kt*QT + tx*4 + j;
                sc[r*SEQ + c] = acc[i][j] + mask[mrow + c];
            }
        }
    }
    __syncthreads();

    const int l  = lena[b];
    const int ly = *layer_p;
    const float ha = hy[ly*3 + 0];
    const float hb = hy[ly*3 + 1];
    const float hc = hy[ly*3 + 2];
    const float* simp = kg + (long)b * 2 * SEQ * SEQ;
    const float* topp = simp + (long)SEQ * SEQ;

    const int warp = tid >> 5, lane = tid & 31;
    for (int r = warp; r < QT; r += 8) {
        float* row = sc + r*SEQ;
        const int qg = q0 + r;

        float mx = -1e30f;
        for (int j = lane; j < SEQ; j += 32) mx = fmaxf(mx, row[j]);
        #pragma unroll
        for (int o = 16; o > 0; o >>= 1) mx = fmaxf(mx, __shfl_xor_sync(0xffffffffu, mx, o));

        float s = 0.f;
        for (int j = lane; j < SEQ; j += 32) {
            float e = __expf(row[j] - mx);
            row[j] = e;
            s += e;
        }
        #pragma unroll
        for (int o = 16; o > 0; o >>= 1) s += __shfl_xor_sync(0xffffffffu, s, o);
        const float inv = 1.0f / s;

        const bool ra_q = (qg >= 1) && (qg < l - 1);
        const bool ca_q = (qg >= l) && (qg < SEQ - 1);
        const long krow = (long)qg * SEQ;
        for (int j = lane; j < SEQ; j += 32) {
            const bool ra_j = (j >= 1) && (j < l - 1);
            const bool ca_j = (j >= l) && (j < SEQ - 1);
            const float lg = ((ra_q && ca_j) || (ra_j && ca_q)) ? hc : 1.0f;
            row[j] = row[j] * inv * lg + ha * simp[krow + j] + hb * topp[krow + j];
        }
    }
    __syncthreads();

    float out[4][4];
    #pragma unroll
    for (int i = 0; i < 4; i++)
        #pragma unroll
        for (int j = 0; j < 4; j++) out[i][j] = 0.f;

    for (int kt = 0; kt < SEQ/QT; kt++) {
        const float* vbase = g_v + head_off + (long)(kt*QT) * HD;
        for (int i = tid; i < QT*16; i += 256) {
            const int r = i >> 4, c = (i & 15) * 4;
            float4 v = *(const float4*)(vbase + r*HD + c);
            Ks[r*65 + c+0] = v.x; Ks[r*65 + c+1] = v.y;
            Ks[r*65 + c+2] = v.z; Ks[r*65 + c+3] = v.w;
        }
        __syncthreads();

        #pragma unroll 8
        for (int jj = 0; jj < QT; jj++) {
            float p[4], vv[4];
            #pragma unroll
            for (int i = 0; i < 4; i++) p[i] = sc[(ty*4+i)*SEQ + kt*QT + jj];
            #pragma unroll
            for (int j = 0; j < 4; j++) vv[j] = Ks[jj*65 + tx*4 + j];
            #pragma unroll
            for (int i = 0; i < 4; i++)
                #pragma unroll
                for (int j = 0; j < 4; j++)
                    out[i][j] += p[i] * vv[j];
        }
        __syncthreads();
    }

    #pragma unroll
    for (int i = 0; i < 4; i++) {
        const int r = q0 + ty*4 + i;
        #pragma unroll
        for (int j = 0; j < 4; j++) {
            g_attn[((long)b*SEQ + r)*HID + h*HD + tx*4 + j] = out[i][j];
        }
    }
}

extern "C" void kernel_launch(void* const* d_in, const int* in_sizes, int n_in,
                              void* d_out, int out_size)
{
    const float* query = (const float*)d_in[0];
    const float* key   = (const float*)d_in[1];
    const float* value = (const float*)d_in[2];
    const float* mask  = (const float*)d_in[3];
    const int*   lena  = (const int*)  d_in[4];
    const float* kg    = (const float*)d_in[5];
    const float* hy    = (const float*)d_in[6];
    const int*   layer = (const int*)  d_in[7];
    const float* Wq    = (const float*)d_in[8];
    const float* bq    = (const float*)d_in[9];
    const float* Wk    = (const float*)d_in[10];
    const float* bk    = (const float*)d_in[11];
    const float* Wv    = (const float*)d_in[12];
    const float* bv    = (const float*)d_in[13];
    const float* Wo    = (const float*)d_in[14];
    const float* bo    = (const float*)d_in[15];
    float* out = (float*)d_out;

    static int smem_set = 0;
    if (!smem_set) {
        cudaFuncSetAttribute(attn_kernel,
                             cudaFuncAttributeMaxDynamicSharedMemorySize, SMEM_ATTN);
        smem_set = 1;
    }

    const dim3 gemm_grid(HID/BN, MROWS/BM);
    const float qscale = 0.125f;

    sgemm_nt<<<gemm_grid, 256>>>(query, Wq, bq, nullptr, HID, qscale, 0);
    sgemm_nt<<<gemm_grid, 256>>>(key,   Wk, bk, nullptr, HID, 1.0f,   1);
    sgemm_nt<<<gemm_grid, 256>>>(value, Wv, bv, nullptr, HID, 1.0f,   2);

    dim3 attn_grid(BATCH*NHEAD, SEQ/QT);
    attn_kernel<<<attn_grid, 256, SMEM_ATTN>>>(mask, kg, lena, hy, layer);

    sgemm_nt<<<gemm_grid, 256>>>(nullptr, Wo, bo, out, HID, 1.0f, 3);
}

// round 3
// speedup vs baseline: 1.7052x; 1.7052x over previous
#include <cuda_runtime.h>
#include <cuda_bf16.h>

#define BATCH 8
#define SEQ   512
#define HID   1024
#define NHEAD 16
#define HD    64
#define MROWS (BATCH*SEQ)

__device__ float g_q[BATCH*NHEAD*SEQ*HD];
__device__ float g_k[BATCH*NHEAD*SEQ*HD];
__device__ float g_v[BATCH*NHEAD*SEQ*HD];
__device__ float g_attn[BATCH*SEQ*HID];

// ===========================================================================
// tf32 tensor-core GEMM:  C[m,n] = scale * (sum_k A[m,k]*W[n,k] + bias[n])
// A: [4096,1024] row-major, W: [1024,1024] row-major (A @ W^T + b)
// 128x128x16 tiles, 8 warps, warp tile 64x32, mma.m16n8k8.tf32
// dst 0..2 -> scatter to g_q/g_k/g_v [B,NH,S,D]; dst 3 -> plain [M,HID]
// ===========================================================================
#define GBK 16
#define KPAD 20

__device__ __forceinline__ unsigned f2tf(float f) {
    unsigned u;
    asm("cvt.rna.tf32.f32 %0, %1;" : "=r"(u) : "f"(f));
    return u;
}

__global__ __launch_bounds__(256, 2)
void gemm_tf32(const float* __restrict__ A, const float* __restrict__ W,
               const float* __restrict__ bias, float* __restrict__ Cout,
               float scale, int dst)
{
    if (A == nullptr) A = g_attn;

    __shared__ unsigned As[2][128 * KPAD];
    __shared__ unsigned Bs[2][128 * KPAD];

    const int tid = threadIdx.x;
    const int bm = blockIdx.y * 128;
    const int bn = blockIdx.x * 128;
    const int wid = tid >> 5, lane = tid & 31;
    const int wm = (wid >> 2) * 64;   // warp row offset (0 or 64)
    const int wn = (wid & 3) * 32;    // warp col offset (0,32,64,96)
    const int gp = lane >> 2;         // 0..7
    const int tg = lane & 3;          // 0..3

    // gmem loader mapping: each thread loads 2 float4 of A and 2 of W per tile
    const int r0 = tid >> 2;          // 0..63
    const int c0 = (tid & 3) * 4;     // 0,4,8,12

    const float* A0 = A + (long)(bm + r0)      * 1024 + c0;
    const float* A1 = A + (long)(bm + r0 + 64) * 1024 + c0;
    const float* W0 = W + (long)(bn + r0)      * 1024 + c0;
    const float* W1 = W + (long)(bn + r0 + 64) * 1024 + c0;

    float acc[4][4][4];
    #pragma unroll
    for (int i = 0; i < 4; i++)
        #pragma unroll
        for (int j = 0; j < 4; j++)
            #pragma unroll
            for (int k = 0; k < 4; k++) acc[i][j][k] = 0.f;

    float4 pa0, pa1, pb0, pb1;

#define STS_TILE(BUF) do {                                                   \
    unsigned* as_ = As[BUF]; unsigned* bs_ = Bs[BUF];                        \
    as_[ r0      *KPAD + c0+0] = f2tf(pa0.x);                                \
    as_[ r0      *KPAD + c0+1] = f2tf(pa0.y);                                \
    as_[ r0      *KPAD + c0+2] = f2tf(pa0.z);                                \
    as_[ r0      *KPAD + c0+3] = f2tf(pa0.w);                                \
    as_[(r0+64)  *KPAD + c0+0] = f2tf(pa1.x);                                \
    as_[(r0+64)  *KPAD + c0+1] = f2tf(pa1.y);                                \
    as_[(r0+64)  *KPAD + c0+2] = f2tf(pa1.z);                                \
    as_[(r0+64)  *KPAD + c0+3] = f2tf(pa1.w);                                \
    bs_[ r0      *KPAD + c0+0] = f2tf(pb0.x);                                \
    bs_[ r0      *KPAD + c0+1] = f2tf(pb0.y);                                \
    bs_[ r0      *KPAD + c0+2] = f2tf(pb0.z);                                \
    bs_[ r0      *KPAD + c0+3] = f2tf(pb0.w);                                \
    bs_[(r0+64)  *KPAD + c0+0] = f2tf(pb1.x);                                \
    bs_[(r0+64)  *KPAD + c0+1] = f2tf(pb1.y);                                \
    bs_[(r0+64)  *KPAD + c0+2] = f2tf(pb1.z);                                \
    bs_[(r0+64)  *KPAD + c0+3] = f2tf(pb1.w);                                \
} while (0)

    pa0 = *(const float4*)(A0);
    pa1 = *(const float4*)(A1);
    pb0 = *(const float4*)(W0);
    pb1 = *(const float4*)(W1);
    STS_TILE(0);
    __syncthreads();

    int buf = 0;
    const int KT = 1024 / GBK;   // 64
    for (int t = 0; t < KT; ++t) {
        if (t < KT - 1) {
            pa0 = *(const float4*)(A0 + (t + 1) * GBK);
            pa1 = *(const float4*)(A1 + (t + 1) * GBK);
            pb0 = *(const float4*)(W0 + (t + 1) * GBK);
            pb1 = *(const float4*)(W1 + (t + 1) * GBK);
        }
        const unsigned* as = As[buf];
        const unsigned* bs = Bs[buf];
        #pragma unroll
        for (int ks = 0; ks < 2; ks++) {
            const int kb = ks * 8;
            unsigned af[4][4], bf[4][2];
            #pragma unroll
            for (int mf = 0; mf < 4; mf++) {
                const int row = wm + mf * 16 + gp;
                af[mf][0] = as[ row      * KPAD + kb + tg];
                af[mf][1] = as[(row + 8) * KPAD + kb + tg];
                af[mf][2] = as[ row      * KPAD + kb + tg + 4];
                af[mf][3] = as[(row + 8) * KPAD + kb + tg + 4];
            }
            #pragma unroll
            for (int nf = 0; nf < 4; nf++) {
                const int row = wn + nf * 8 + gp;
                bf[nf][0] = bs[row * KPAD + kb + tg];
                bf[nf][1] = bs[row * KPAD + kb + tg + 4];
            }
            #pragma unroll
            for (int mf = 0; mf < 4; mf++)
                #pragma unroll
                for (int nf = 0; nf < 4; nf++)
                    asm volatile(
                        "mma.sync.aligned.m16n8k8.row.col.f32.tf32.tf32.f32 "
                        "{%0,%1,%2,%3}, {%4,%5,%6,%7}, {%8,%9}, {%0,%1,%2,%3};"
                        : "+f"(acc[mf][nf][0]), "+f"(acc[mf][nf][1]),
                          "+f"(acc[mf][nf][2]), "+f"(acc[mf][nf][3])
                        : "r"(af[mf][0]), "r"(af[mf][1]),
                          "r"(af[mf][2]), "r"(af[mf][3]),
                          "r"(bf[nf][0]), "r"(bf[nf][1]));
        }
        if (t < KT - 1) STS_TILE(buf ^ 1);
        __syncthreads();
        buf ^= 1;
    }
#undef STS_TILE

    float* Cq = (dst == 0) ? g_q : (dst == 1) ? g_k : g_v;

    #pragma unroll
    for (int mf = 0; mf < 4; mf++) {
        #pragma unroll
        for (int nf = 0; nf < 4; nf++) {
            const int n0 = bn + wn + nf * 8 + tg * 2;   // even
            const float b0 = bias[n0], b1 = bias[n0 + 1];
            #pragma unroll
            for (int half = 0; half < 2; half++) {
                const int m = bm + wm + mf * 16 + gp + half * 8;
                const float v0 = (acc[mf][nf][half * 2 + 0] + b0) * scale;
                const float v1 = (acc[mf][nf][half * 2 + 1] + b1) * scale;
                if (dst < 3) {
                    const int b = m >> 9, s = m & 511;
                    const int h = n0 >> 6, d = n0 & 63;
                    const long base = (((long)(b * NHEAD + h)) * SEQ + s) * HD;
                    Cq[base + d]     = v0;
                    Cq[base + d + 1] = v1;
                } else {
                    Cout[(long)m * HID + n0]     = v0;
                    Cout[(long)m * HID + n0 + 1] = v1;
                }
            }
        }
    }
}

// ===========================================================================
// Fused attention: per block = (b, h, 32-query tile).  smem ~88.4KB -> 2 CTA/SM
// ===========================================================================
#define QT 32
#define SMEM_ATTN ((QT*SEQ + QT*65 + 64*65) * (int)sizeof(float))

__global__ __launch_bounds__(256)
void attn_kernel(const float* __restrict__ mask, const float* __restrict__ kg,
                 const int* __restrict__ lena, const float* __restrict__ hy,
                 const int* __restrict__ layer_p)
{
    extern __shared__ float sm[];
    float* sc = sm;                    // [32][512]
    float* Qs = sm + QT * SEQ;         // [32][65]
    float* Ks = Qs + QT * 65;          // [64][65] (reused for V)

    const int tid = threadIdx.x;
    const int bh = blockIdx.x;
    const int b = bh >> 4, h = bh & 15;
    const int q0 = blockIdx.y * QT;

    const long head_off = ((long)(b * NHEAD + h)) * SEQ * HD;
    const float* qbase = g_q + head_off + (long)q0 * HD;

    // load Q tile (32x64, pre-scaled by 1/sqrt(D))
    for (int i = tid; i < QT * 16; i += 256) {
        const int r = i >> 4, c = (i & 15) * 4;
        float4 v = *(const float4*)(qbase + r * HD + c);
        Qs[r*65 + c+0] = v.x; Qs[r*65 + c+1] = v.y;
        Qs[r*65 + c+2] = v.z; Qs[r*65 + c+3] = v.w;
    }

    const int tx = tid & 15, ty = tid >> 4;   // rows ty*2+{0,1}, cols tx*4+{0..3}

    // ---- scores = Q K^T + mask ----
    for (int kt = 0; kt < SEQ / 64; kt++) {
        const float* kbase = g_k + head_off + (long)(kt * 64) * HD;
        __syncthreads();
        for (int i = tid; i < 64 * 16; i += 256) {
            const int r = i >> 4, c = (i & 15) * 4;
            float4 v = *(const float4*)(kbase + r * HD + c);
            Ks[r*65 + c+0] = v.x; Ks[r*65 + c+1] = v.y;
            Ks[r*65 + c+2] = v.z; Ks[r*65 + c+3] = v.w;
        }
        __syncthreads();

        float acc[2][4];
        #pragma unroll
        for (int i = 0; i < 2; i++)
            #pragma unroll
            for (int j = 0; j < 4; j++) acc[i][j] = 0.f;

        #pragma unroll 8
        for (int d = 0; d < HD; d++) {
            float qv[2], kv[4];
            #pragma unroll
            for (int i = 0; i < 2; i++) qv[i] = Qs[(ty*2+i)*65 + d];
            #pragma unroll
            for (int j = 0; j < 4; j++) kv[j] = Ks[(tx*4+j)*65 + d];
            #pragma unroll
            for (int i = 0; i < 2; i++)
                #pragma unroll
                for (int j = 0; j < 4; j++)
                    acc[i][j] += qv[i] * kv[j];
        }

        #pragma unroll
        for (int i = 0; i < 2; i++) {
            const int r = ty*2 + i;
            const long mrow = ((long)b * SEQ + (q0 + r)) * SEQ;
            #pragma unroll
            for (int j = 0; j < 4; j++) {
                const int c = kt*64 + tx*4 + j;
                sc[r*SEQ + c] = acc[i][j] + mask[mrow + c];
            }
        }
    }
    __syncthreads();

    // ---- softmax + probs mods (in place) ----
    const int l  = lena[b];
    const int ly = *layer_p;
    const float ha = hy[ly*3 + 0];
    const float hb = hy[ly*3 + 1];
    const float hc = hy[ly*3 + 2];
    const float* simp = kg + (long)b * 2 * SEQ * SEQ;
    const float* topp = simp + (long)SEQ * SEQ;

    const int warp = tid >> 5, lane = tid & 31;
    for (int r = warp; r < QT; r += 8) {
        float* row = sc + r * SEQ;
        const int qg = q0 + r;

        float mx = -1e30f;
        for (int j = lane; j < SEQ; j += 32) mx = fmaxf(mx, row[j]);
        #pragma unroll
        for (int o = 16; o > 0; o >>= 1) mx = fmaxf(mx, __shfl_xor_sync(0xffffffffu, mx, o));

        float s = 0.f;
        for (int j = lane; j < SEQ; j += 32) {
            float e = __expf(row[j] - mx);
            row[j] = e;
            s += e;
        }
        #pragma unroll
        for (int o = 16; o > 0; o >>= 1) s += __shfl_xor_sync(0xffffffffu, s, o);
        const float inv = 1.0f / s;

        const bool ra_q = (qg >= 1) && (qg < l - 1);
        const bool ca_q = (qg >= l) && (qg < SEQ - 1);
        const long krow = (long)qg * SEQ;
        for (int j = lane; j < SEQ; j += 32) {
            const bool ra_j = (j >= 1) && (j < l - 1);
            const bool ca_j = (j >= l) && (j < SEQ - 1);
            const float lg = ((ra_q && ca_j) || (ra_j && ca_q)) ? hc : 1.0f;
            row[j] = row[j] * inv * lg + ha * simp[krow + j] + hb * topp[krow + j];
        }
    }
    __syncthreads();

    // ---- out = P V ----
    float out[2][4];
    #pragma unroll
    for (int i = 0; i < 2; i++)
        #pragma unroll
        for (int j = 0; j < 4; j++) out[i][j] = 0.f;

    for (int kt = 0; kt < SEQ / 64; kt++) {
        const float* vbase = g_v + head_off + (long)(kt * 64) * HD;
        for (int i = tid; i < 64 * 16; i += 256) {
            const int r = i >> 4, c = (i & 15) * 4;
            float4 v = *(const float4*)(vbase + r * HD + c);
            Ks[r*65 + c+0] = v.x; Ks[r*65 + c+1] = v.y;
            Ks[r*65 + c+2] = v.z; Ks[r*65 + c+3] = v.w;
        }
        __syncthreads();

        #pragma unroll 8
        for (int jj = 0; jj < 64; jj++) {
            float p[2], vv[4];
            #pragma unroll
            for (int i = 0; i < 2; i++) p[i] = sc[(ty*2+i)*SEQ + kt*64 + jj];
            #pragma unroll
            for (int j = 0; j < 4; j++) vv[j] = Ks[jj*65 + tx*4 + j];
            #pragma unroll
            for (int i = 0; i < 2; i++)
                #pragma unroll
                for (int j = 0; j < 4; j++)
                    out[i][j] += p[i] * vv[j];
        }
        __syncthreads();
    }

    #pragma unroll
    for (int i = 0; i < 2; i++) {
        const int r = q0 + ty*2 + i;
        #pragma unroll
        for (int j = 0; j < 4; j++) {
            g_attn[((long)b * SEQ + r) * HID + h * HD + tx*4 + j] = out[i][j];
        }
    }
}

// ===========================================================================
extern "C" void kernel_launch(void* const* d_in, const int* in_sizes, int n_in,
                              void* d_out, int out_size)
{
    const float* query = (const float*)d_in[0];
    const float* key   = (const float*)d_in[1];
    const float* value = (const float*)d_in[2];
    const float* mask  = (const float*)d_in[3];
    const int*   lena  = (const int*)  d_in[4];
    const float* kg    = (const float*)d_in[5];
    const float* hy    = (const float*)d_in[6];
    const int*   layer = (const int*)  d_in[7];
    const float* Wq    = (const float*)d_in[8];
    const float* bq    = (const float*)d_in[9];
    const float* Wk    = (const float*)d_in[10];
    const float* bk    = (const float*)d_in[11];
    const float* Wv    = (const float*)d_in[12];
    const float* bv    = (const float*)d_in[13];
    const float* Wo    = (const float*)d_in[14];
    const float* bo    = (const float*)d_in[15];
    float* out = (float*)d_out;

    static int smem_set = 0;
    if (!smem_set) {
        cudaFuncSetAttribute(attn_kernel,
                             cudaFuncAttributeMaxDynamicSharedMemorySize, SMEM_ATTN);
        smem_set = 1;
    }

    const dim3 ggrid(HID / 128, MROWS / 128);   // (8, 32)
    const float qscale = 0.125f;                // 1/sqrt(64)

    gemm_tf32<<<ggrid, 256>>>(query, Wq, bq, nullptr, qscale, 0);
    gemm_tf32<<<ggrid, 256>>>(key,   Wk, bk, nullptr, 1.0f,   1);
    gemm_tf32<<<ggrid, 256>>>(value, Wv, bv, nullptr, 1.0f,   2);

    dim3 attn_grid(BATCH * NHEAD, SEQ / QT);    // (128, 16)
    attn_kernel<<<attn_grid, 256, SMEM_ATTN>>>(mask, kg, lena, hy, layer);

    gemm_tf32<<<ggrid, 256>>>(nullptr, Wo, bo, out, 1.0f, 3);
}

// round 4
// speedup vs baseline: 1.9349x; 1.1347x over previous
#include <cuda_runtime.h>
#include <cuda_bf16.h>

#define BATCH 8
#define SEQ   512
#define HID   1024
#define NHEAD 16
#define HD    64
#define MROWS (BATCH*SEQ)

__device__ float g_q[BATCH*NHEAD*SEQ*HD];
__device__ float g_k[BATCH*NHEAD*SEQ*HD];
__device__ float g_v[BATCH*NHEAD*SEQ*HD];
__device__ float g_attn[BATCH*SEQ*HID];

__device__ __forceinline__ unsigned f2tf(float f) {
    unsigned u;
    asm("cvt.rna.tf32.f32 %0, %1;" : "=r"(u) : "f"(f));
    return u;
}

// split fp32 -> (hi, lo) tf32 pair (Markidis)
__device__ __forceinline__ void ldsplit(const float* p, unsigned& hi, unsigned& lo) {
    float v = *p;
    hi = f2tf(v);
    lo = f2tf(v - __uint_as_float(hi));
}

__device__ __forceinline__ void mma8(float* c, const unsigned* a, const unsigned* b) {
    asm volatile(
        "mma.sync.aligned.m16n8k8.row.col.f32.tf32.tf32.f32 "
        "{%0,%1,%2,%3}, {%4,%5,%6,%7}, {%8,%9}, {%0,%1,%2,%3};"
        : "+f"(c[0]), "+f"(c[1]), "+f"(c[2]), "+f"(c[3])
        : "r"(a[0]), "r"(a[1]), "r"(a[2]), "r"(a[3]), "r"(b[0]), "r"(b[1]));
}

// ===========================================================================
// tf32 tensor-core GEMM (unchanged from R3):
// C[m,n] = scale * (sum_k A[m,k]*W[n,k] + bias[n]); dst 0..2 scatter, 3 plain
// ===========================================================================
#define GBK 16
#define KPAD 20

__global__ __launch_bounds__(256, 2)
void gemm_tf32(const float* __restrict__ A, const float* __restrict__ W,
               const float* __restrict__ bias, float* __restrict__ Cout,
               float scale, int dst)
{
    if (A == nullptr) A = g_attn;

    __shared__ unsigned As[2][128 * KPAD];
    __shared__ unsigned Bs[2][128 * KPAD];

    const int tid = threadIdx.x;
    const int bm = blockIdx.y * 128;
    const int bn = blockIdx.x * 128;
    const int wid = tid >> 5, lane = tid & 31;
    const int wm = (wid >> 2) * 64;
    const int wn = (wid & 3) * 32;
    const int gp = lane >> 2;
    const int tg = lane & 3;

    const int r0 = tid >> 2;
    const int c0 = (tid & 3) * 4;

    const float* A0 = A + (long)(bm + r0)      * 1024 + c0;
    const float* A1 = A + (long)(bm + r0 + 64) * 1024 + c0;
    const float* W0 = W + (long)(bn + r0)      * 1024 + c0;
    const float* W1 = W + (long)(bn + r0 + 64) * 1024 + c0;

    float acc[4][4][4];
    #pragma unroll
    for (int i = 0; i < 4; i++)
        #pragma unroll
        for (int j = 0; j < 4; j++)
            #pragma unroll
            for (int k = 0; k < 4; k++) acc[i][j][k] = 0.f;

    float4 pa0, pa1, pb0, pb1;

#define STS_TILE(BUF) do {                                                   \
    unsigned* as_ = As[BUF]; unsigned* bs_ = Bs[BUF];                        \
    as_[ r0      *KPAD + c0+0] = f2tf(pa0.x);                                \
    as_[ r0      *KPAD + c0+1] = f2tf(pa0.y);                                \
    as_[ r0      *KPAD + c0+2] = f2tf(pa0.z);                                \
    as_[ r0      *KPAD + c0+3] = f2tf(pa0.w);                                \
    as_[(r0+64)  *KPAD + c0+0] = f2tf(pa1.x);                                \
    as_[(r0+64)  *KPAD + c0+1] = f2tf(pa1.y);                                \
    as_[(r0+64)  *KPAD + c0+2] = f2tf(pa1.z);                                \
    as_[(r0+64)  *KPAD + c0+3] = f2tf(pa1.w);                                \
    bs_[ r0      *KPAD + c0+0] = f2tf(pb0.x);                                \
    bs_[ r0      *KPAD + c0+1] = f2tf(pb0.y);                                \
    bs_[ r0      *KPAD + c0+2] = f2tf(pb0.z);                                \
    bs_[ r0      *KPAD + c0+3] = f2tf(pb0.w);                                \
    bs_[(r0+64)  *KPAD + c0+0] = f2tf(pb1.x);                                \
    bs_[(r0+64)  *KPAD + c0+1] = f2tf(pb1.y);                                \
    bs_[(r0+64)  *KPAD + c0+2] = f2tf(pb1.z);                                \
    bs_[(r0+64)  *KPAD + c0+3] = f2tf(pb1.w);                                \
} while (0)

    pa0 = *(const float4*)(A0);
    pa1 = *(const float4*)(A1);
    pb0 = *(const float4*)(W0);
    pb1 = *(const float4*)(W1);
    STS_TILE(0);
    __syncthreads();

    int buf = 0;
    const int KT = 1024 / GBK;
    for (int t = 0; t < KT; ++t) {
        if (t < KT - 1) {
            pa0 = *(const float4*)(A0 + (t + 1) * GBK);
            pa1 = *(const float4*)(A1 + (t + 1) * GBK);
            pb0 = *(const float4*)(W0 + (t + 1) * GBK);
            pb1 = *(const float4*)(W1 + (t + 1) * GBK);
        }
        const unsigned* as = As[buf];
        const unsigned* bs = Bs[buf];
        #pragma unroll
        for (int ks = 0; ks < 2; ks++) {
            const int kb = ks * 8;
            unsigned af[4][4], bf[4][2];
            #pragma unroll
            for (int mf = 0; mf < 4; mf++) {
                const int row = wm + mf * 16 + gp;
                af[mf][0] = as[ row      * KPAD + kb + tg];
                af[mf][1] = as[(row + 8) * KPAD + kb + tg];
                af[mf][2] = as[ row      * KPAD + kb + tg + 4];
                af[mf][3] = as[(row + 8) * KPAD + kb + tg + 4];
            }
            #pragma unroll
            for (int nf = 0; nf < 4; nf++) {
                const int row = wn + nf * 8 + gp;
                bf[nf][0] = bs[row * KPAD + kb + tg];
                bf[nf][1] = bs[row * KPAD + kb + tg + 4];
            }
            #pragma unroll
            for (int mf = 0; mf < 4; mf++)
                #pragma unroll
                for (int nf = 0; nf < 4; nf++)
                    mma8(acc[mf][nf], af[mf], bf[nf]);
        }
        if (t < KT - 1) STS_TILE(buf ^ 1);
        __syncthreads();
        buf ^= 1;
    }
#undef STS_TILE

    float* Cq = (dst == 0) ? g_q : (dst == 1) ? g_k : g_v;

    #pragma unroll
    for (int mf = 0; mf < 4; mf++) {
        #pragma unroll
        for (int nf = 0; nf < 4; nf++) {
            const int n0 = bn + wn + nf * 8 + tg * 2;
            const float b0 = bias[n0], b1 = bias[n0 + 1];
            #pragma unroll
            for (int half = 0; half < 2; half++) {
                const int m = bm + wm + mf * 16 + gp + half * 8;
                const float v0 = (acc[mf][nf][half * 2 + 0] + b0) * scale;
                const float v1 = (acc[mf][nf][half * 2 + 1] + b1) * scale;
                if (dst < 3) {
                    const int b = m >> 9, s = m & 511;
                    const int h = n0 >> 6, d = n0 & 63;
                    const long base = (((long)(b * NHEAD + h)) * SEQ + s) * HD;
                    Cq[base + d]     = v0;
                    Cq[base + d + 1] = v1;
                } else {
                    Cout[(long)m * HID + n0]     = v0;
                    Cout[(long)m * HID + n0 + 1] = v1;
                }
            }
        }
    }
}

// ===========================================================================
// mma-based fused attention. Block = (b, h, 64-query tile). 8 warps.
// smem: sc[64][516] fp32 + Qs[64][72] + Ks[64][72] (K, then reused for V)
// QK^T and P*V via split-tf32 mma (3-term Markidis -> ~fp32 accuracy).
// ===========================================================================
#define SCP 516
#define KVP 72
#define SMEM_ATTN ((64*SCP + 2*64*KVP) * (int)sizeof(float))

__global__ __launch_bounds__(256)
void attn_mma(const float* __restrict__ mask, const float* __restrict__ kg,
              const int* __restrict__ lena, const float* __restrict__ hy,
              const int* __restrict__ layer_p)
{
    extern __shared__ float sm[];
    float* sc = sm;                  // [64][516]
    float* Qs = sm + 64 * SCP;       // [64][72]
    float* Ks = Qs + 64 * KVP;       // [64][72]

    const int tid = threadIdx.x;
    const int bh = blockIdx.x;
    const int b = bh >> 4, h = bh & 15;
    const int q0 = blockIdx.y * 64;

    const long head_off = ((long)(b * NHEAD + h)) * SEQ * HD;

    const int wid = tid >> 5, lane = tid & 31;
    const int gp = lane >> 3 ? (lane >> 2) : (lane >> 2); // = lane>>2
    const int g8 = lane >> 2;        // 0..7
    const int tg = lane & 3;         // 0..3
    const int wm = (wid >> 2) * 32;  // 0 or 32
    const int wn = (wid & 3) * 16;   // 0,16,32,48
    (void)gp;

    // tile loader mapping: row = tid>>2 (0..63), 16 consecutive cols per thread
    const int lr = tid >> 2;
    const int lcb = (tid & 3) * 16;

    // ---- load Q tile (64x64) ----
    {
        const float* qbase = g_q + head_off + (long)q0 * HD + (long)lr * HD + lcb;
        #pragma unroll
        for (int i = 0; i < 4; i++) {
            float4 v = *(const float4*)(qbase + i * 4);
            Qs[lr * KVP + lcb + i*4 + 0] = v.x;
            Qs[lr * KVP + lcb + i*4 + 1] = v.y;
            Qs[lr * KVP + lcb + i*4 + 2] = v.z;
            Qs[lr * KVP + lcb + i*4 + 3] = v.w;
        }
    }

    // ================= Phase 1: scores = Q K^T + mask =================
    {
        const float* kbase = g_k + head_off + (long)lr * HD + lcb;
        float4 pf[4];
        #pragma unroll
        for (int i = 0; i < 4; i++) pf[i] = *(const float4*)(kbase + i * 4);

        for (int kt = 0; kt < 8; kt++) {
            __syncthreads();
            #pragma unroll
            for (int i = 0; i < 4; i++) {
                Ks[lr * KVP + lcb + i*4 + 0] = pf[i].x;
                Ks[lr * KVP + lcb + i*4 + 1] = pf[i].y;
                Ks[lr * KVP + lcb + i*4 + 2] = pf[i].z;
                Ks[lr * KVP + lcb + i*4 + 3] = pf[i].w;
            }
            __syncthreads();
            if (kt < 7) {
                const float* nb = kbase + (long)(kt + 1) * 64 * HD;
                #pragma unroll
                for (int i = 0; i < 4; i++) pf[i] = *(const float4*)(nb + i * 4);
            }

            float acc[2][2][4];
            #pragma unroll
            for (int mf = 0; mf < 2; mf++)
                #pragma unroll
                for (int nf = 0; nf < 2; nf++)
                    #pragma unroll
                    for (int k = 0; k < 4; k++) acc[mf][nf][k] = 0.f;

            #pragma unroll 2
            for (int kb = 0; kb < 64; kb += 8) {
                unsigned ah[2][4], al[2][4], bhc[2][2], blc[2][2];
                #pragma unroll
                for (int mf = 0; mf < 2; mf++) {
                    const float* base = Qs + (wm + mf*16 + g8) * KVP + kb + tg;
                    ldsplit(base,           ah[mf][0], al[mf][0]);
                    ldsplit(base + 8*KVP,   ah[mf][1], al[mf][1]);
                    ldsplit(base + 4,       ah[mf][2], al[mf][2]);
                    ldsplit(base + 8*KVP+4, ah[mf][3], al[mf][3]);
                }
                #pragma unroll
                for (int nf = 0; nf < 2; nf++) {
                    const float* base = Ks + (wn + nf*8 + g8) * KVP + kb + tg;
                    ldsplit(base,     bhc[nf][0], blc[nf][0]);
                    ldsplit(base + 4, bhc[nf][1], blc[nf][1]);
                }
                #pragma unroll
                for (int mf = 0; mf < 2; mf++)
                    #pragma unroll
                    for (int nf = 0; nf < 2; nf++) {
                        mma8(acc[mf][nf], ah[mf], bhc[nf]);
                        mma8(acc[mf][nf], ah[mf], blc[nf]);
                        mma8(acc[mf][nf], al[mf], bhc[nf]);
                    }
            }

            // write scores (+mask) to sc
            #pragma unroll
            for (int mf = 0; mf < 2; mf++)
                #pragma unroll
                for (int nf = 0; nf < 2; nf++) {
                    const int c = kt*64 + wn + nf*8 + 2*tg;
                    #pragma unroll
                    for (int half = 0; half < 2; half++) {
                        const int r = wm + mf*16 + g8 + half*8;
                        const long mrow = ((long)b * SEQ + (q0 + r)) * SEQ;
                        sc[r*SCP + c]     = acc[mf][nf][half*2+0] + mask[mrow + c];
                        sc[r*SCP + c + 1] = acc[mf][nf][half*2+1] + mask[mrow + c + 1];
                    }
                }
        }
    }
    __syncthreads();

    // ================= Phase 2: softmax + probs mods =================
    {
        const int l  = lena[b];
        const int ly = *layer_p;
        const float ha = hy[ly*3 + 0];
        const float hb = hy[ly*3 + 1];
        const float hc = hy[ly*3 + 2];
        const float* simp = kg + (long)b * 2 * SEQ * SEQ;
        const float* topp = simp + (long)SEQ * SEQ;

        for (int r = wid; r < 64; r += 8) {
            float* row = sc + r * SCP;
            const int qg = q0 + r;

            float mx = -1e30f;
            #pragma unroll 4
            for (int j = lane; j < SEQ; j += 32) mx = fmaxf(mx, row[j]);
            #pragma unroll
            for (int o = 16; o > 0; o >>= 1) mx = fmaxf(mx, __shfl_xor_sync(0xffffffffu, mx, o));

            float s = 0.f;
            #pragma unroll 4
            for (int j = lane; j < SEQ; j += 32) {
                float e = __expf(row[j] - mx);
                row[j] = e;
                s += e;
            }
            #pragma unroll
            for (int o = 16; o > 0; o >>= 1) s += __shfl_xor_sync(0xffffffffu, s, o);
            const float inv = 1.0f / s;

            const bool ra_q = (qg >= 1) && (qg < l - 1);
            const bool ca_q = (qg >= l) && (qg < SEQ - 1);
            const long krow = (long)qg * SEQ;
            #pragma unroll 4
            for (int j = lane; j < SEQ; j += 32) {
                const bool ra_j = (j >= 1) && (j < l - 1);
                const bool ca_j = (j >= l) && (j < SEQ - 1);
                const float lg = ((ra_q && ca_j) || (ra_j && ca_q)) ? hc : 1.0f;
                row[j] = row[j] * inv * lg + ha * simp[krow + j] + hb * topp[krow + j];
            }
        }
    }

    // ================= Phase 3: out = P V =================
    {
        float oacc[2][2][4];
        #pragma unroll
        for (int mf = 0; mf < 2; mf++)
            #pragma unroll
            for (int nf = 0; nf < 2; nf++)
                #pragma unroll
                for (int k = 0; k < 4; k++) oacc[mf][nf][k] = 0.f;

        const float* vbase = g_v + head_off + (long)lr * HD + lcb;
        float4 pf[4];
        #pragma unroll
        for (int i = 0; i < 4; i++) pf[i] = *(const float4*)(vbase + i * 4);

        for (int kt = 0; kt < 8; kt++) {
            __syncthreads();
            #pragma unroll
            for (int i = 0; i < 4; i++) {
                Ks[lr * KVP + lcb + i*4 + 0] = pf[i].x;
                Ks[lr * KVP + lcb + i*4 + 1] = pf[i].y;
                Ks[lr * KVP + lcb + i*4 + 2] = pf[i].z;
                Ks[lr * KVP + lcb + i*4 + 3] = pf[i].w;
            }
            __syncthreads();
            if (kt < 7) {
                const float* nb = vbase + (long)(kt + 1) * 64 * HD;
                #pragma unroll
                for (int i = 0; i < 4; i++) pf[i] = *(const float4*)(nb + i * 4);
            }

            #pragma unroll 2
            for (int kb = 0; kb < 64; kb += 8) {
                unsigned ah[2][4], al[2][4], bhc[2][2], blc[2][2];
                #pragma unroll
                for (int mf = 0; mf < 2; mf++) {
                    const float* base = sc + (wm + mf*16 + g8) * SCP + kt*64 + kb + tg;
                    ldsplit(base,           ah[mf][0], al[mf][0]);
                    ldsplit(base + 8*SCP,   ah[mf][1], al[mf][1]);
                    ldsplit(base + 4,       ah[mf][2], al[mf][2]);
                    ldsplit(base + 8*SCP+4, ah[mf][3], al[mf][3]);
                }
                #pragma unroll
                for (int nf = 0; nf < 2; nf++) {
                    const float* base = Ks + (kb + tg) * KVP + wn + nf*8 + g8;
                    ldsplit(base,          bhc[nf][0], blc[nf][0]);
                    ldsplit(base + 4*KVP,  bhc[nf][1], blc[nf][1]);
                }
                #pragma unroll
                for (int mf = 0; mf < 2; mf++)
                    #pragma unroll
                    for (int nf = 0; nf < 2; nf++) {
                        mma8(oacc[mf][nf], ah[mf], bhc[nf]);
                        mma8(oacc[mf][nf], ah[mf], blc[nf]);
                        mma8(oacc[mf][nf], al[mf], bhc[nf]);
                    }
            }
        }

        // epilogue: write O tile to g_attn [B,S,H]
        #pragma unroll
        for (int mf = 0; mf < 2; mf++)
            #pragma unroll
            for (int nf = 0; nf < 2; nf++) {
                const int d0 = wn + nf*8 + 2*tg;
                #pragma unroll
                for (int half = 0; half < 2; half++) {
                    const int r = q0 + wm + mf*16 + g8 + half*8;
                    float* dst = g_attn + ((long)b * SEQ + r) * HID + h * HD + d0;
                    dst[0] = oacc[mf][nf][half*2+0];
                    dst[1] = oacc[mf][nf][half*2+1];
                }
            }
    }
}

// ===========================================================================
extern "C" void kernel_launch(void* const* d_in, const int* in_sizes, int n_in,
                              void* d_out, int out_size)
{
    const float* query = (const float*)d_in[0];
    const float* key   = (const float*)d_in[1];
    const float* value = (const float*)d_in[2];
    const float* mask  = (const float*)d_in[3];
    const int*   lena  = (const int*)  d_in[4];
    const float* kg    = (const float*)d_in[5];
    const float* hy    = (const float*)d_in[6];
    const int*   layer = (const int*)  d_in[7];
    const float* Wq    = (const float*)d_in[8];
    const float* bq    = (const float*)d_in[9];
    const float* Wk    = (const float*)d_in[10];
    const float* bk    = (const float*)d_in[11];
    const float* Wv    = (const float*)d_in[12];
    const float* bv    = (const float*)d_in[13];
    const float* Wo    = (const float*)d_in[14];
    const float* bo    = (const float*)d_in[15];
    float* out = (float*)d_out;

    static int smem_set = 0;
    if (!smem_set) {
        cudaFuncSetAttribute(attn_mma,
                             cudaFuncAttributeMaxDynamicSharedMemorySize, SMEM_ATTN);
        smem_set = 1;
    }

    const dim3 ggrid(HID / 128, MROWS / 128);   // (8, 32)
    const float qscale = 0.125f;                // 1/sqrt(64)

    gemm_tf32<<<ggrid, 256>>>(query, Wq, bq, nullptr, qscale, 0);
    gemm_tf32<<<ggrid, 256>>>(key,   Wk, bk, nullptr, 1.0f,   1);
    gemm_tf32<<<ggrid, 256>>>(value, Wv, bv, nullptr, 1.0f,   2);

    dim3 attn_grid(BATCH * NHEAD, SEQ / 64);    // (128, 8)
    attn_mma<<<attn_grid, 256, SMEM_ATTN>>>(mask, kg, lena, hy, layer);

    gemm_tf32<<<ggrid, 256>>>(nullptr, Wo, bo, out, 1.0f, 3);
}

// round 6
// speedup vs baseline: 2.4052x; 1.2430x over previous
#include <cuda_runtime.h>
#include <cuda_bf16.h>

#define BATCH 8
#define SEQ   512
#define HID   1024
#define NHEAD 16
#define HD    64
#define MROWS (BATCH*SEQ)

__device__ float g_q[BATCH*NHEAD*SEQ*HD];
__device__ float g_k[BATCH*NHEAD*SEQ*HD];
__device__ float g_v[BATCH*NHEAD*SEQ*HD];
__device__ float g_attn[BATCH*SEQ*HID];

__device__ __forceinline__ unsigned f2tf(float f) {
    unsigned u;
    asm("cvt.rna.tf32.f32 %0, %1;" : "=r"(u) : "f"(f));
    return u;
}

__device__ __forceinline__ void mma8(float* c, const unsigned* a, const unsigned* b) {
    asm volatile(
        "mma.sync.aligned.m16n8k8.row.col.f32.tf32.tf32.f32 "
        "{%0,%1,%2,%3}, {%4,%5,%6,%7}, {%8,%9}, {%0,%1,%2,%3};"
        : "+f"(c[0]), "+f"(c[1]), "+f"(c[2]), "+f"(c[3])
        : "r"(a[0]), "r"(a[1]), "r"(a[2]), "r"(a[3]), "r"(b[0]), "r"(b[1]));
}

// ===========================================================================
// tf32 tensor-core GEMM:
// C[m,n] = scale * (sum_k A[m,k]*W[n,k] + bias[n]); dst 0..2 scatter, 3 plain
// ===========================================================================
#define GBK 16
#define KPAD 20

__global__ __launch_bounds__(256, 2)
void gemm_tf32(const float* __restrict__ A, const float* __restrict__ W,
               const float* __restrict__ bias, float* __restrict__ Cout,
               float scale, int dst)
{
    if (A == nullptr) A = g_attn;

    __shared__ unsigned As[2][128 * KPAD];
    __shared__ unsigned Bs[2][128 * KPAD];

    const int tid = threadIdx.x;
    const int bm = blockIdx.y * 128;
    const int bn = blockIdx.x * 128;
    const int wid = tid >> 5, lane = tid & 31;
    const int wm = (wid >> 2) * 64;
    const int wn = (wid & 3) * 32;
    const int gp = lane >> 2;
    const int tg = lane & 3;

    const int r0 = tid >> 2;
    const int c0 = (tid & 3) * 4;

    const float* A0 = A + (long)(bm + r0)      * 1024 + c0;
    const float* A1 = A + (long)(bm + r0 + 64) * 1024 + c0;
    const float* W0 = W + (long)(bn + r0)      * 1024 + c0;
    const float* W1 = W + (long)(bn + r0 + 64) * 1024 + c0;

    float acc[4][4][4];
    #pragma unroll
    for (int i = 0; i < 4; i++)
        #pragma unroll
        for (int j = 0; j < 4; j++)
            #pragma unroll
            for (int k = 0; k < 4; k++) acc[i][j][k] = 0.f;

    float4 pa0, pa1, pb0, pb1;

#define STS_TILE(BUF) do {                                                   \
    unsigned* as_ = As[BUF]; unsigned* bs_ = Bs[BUF];                        \
    as_[ r0      *KPAD + c0+0] = f2tf(pa0.x);                                \
    as_[ r0      *KPAD + c0+1] = f2tf(pa0.y);                                \
    as_[ r0      *KPAD + c0+2] = f2tf(pa0.z);                                \
    as_[ r0      *KPAD + c0+3] = f2tf(pa0.w);                                \
    as_[(r0+64)  *KPAD + c0+0] = f2tf(pa1.x);                                \
    as_[(r0+64)  *KPAD + c0+1] = f2tf(pa1.y);                                \
    as_[(r0+64)  *KPAD + c0+2] = f2tf(pa1.z);                                \
    as_[(r0+64)  *KPAD + c0+3] = f2tf(pa1.w);                                \
    bs_[ r0      *KPAD + c0+0] = f2tf(pb0.x);                                \
    bs_[ r0      *KPAD + c0+1] = f2tf(pb0.y);                                \
    bs_[ r0      *KPAD + c0+2] = f2tf(pb0.z);                                \
    bs_[ r0      *KPAD + c0+3] = f2tf(pb0.w);                                \
    bs_[(r0+64)  *KPAD + c0+0] = f2tf(pb1.x);                                \
    bs_[(r0+64)  *KPAD + c0+1] = f2tf(pb1.y);                                \
    bs_[(r0+64)  *KPAD + c0+2] = f2tf(pb1.z);                                \
    bs_[(r0+64)  *KPAD + c0+3] = f2tf(pb1.w);                                \
} while (0)

    pa0 = *(const float4*)(A0);
    pa1 = *(const float4*)(A1);
    pb0 = *(const float4*)(W0);
    pb1 = *(const float4*)(W1);
    STS_TILE(0);
    __syncthreads();

    int buf = 0;
    const int KT = 1024 / GBK;
    for (int t = 0; t < KT; ++t) {
        if (t < KT - 1) {
            pa0 = *(const float4*)(A0 + (t + 1) * GBK);
            pa1 = *(const float4*)(A1 + (t + 1) * GBK);
            pb0 = *(const float4*)(W0 + (t + 1) * GBK);
            pb1 = *(const float4*)(W1 + (t + 1) * GBK);
        }
        const unsigned* as = As[buf];
        const unsigned* bs = Bs[buf];
        #pragma unroll
        for (int ks = 0; ks < 2; ks++) {
            const int kb = ks * 8;
            unsigned af[4][4], bf[4][2];
            #pragma unroll
            for (int mf = 0; mf < 4; mf++) {
                const int row = wm + mf * 16 + gp;
                af[mf][0] = as[ row      * KPAD + kb + tg];
                af[mf][1] = as[(row + 8) * KPAD + kb + tg];
                af[mf][2] = as[ row      * KPAD + kb + tg + 4];
                af[mf][3] = as[(row + 8) * KPAD + kb + tg + 4];
            }
            #pragma unroll
            for (int nf = 0; nf < 4; nf++) {
                const int row = wn + nf * 8 + gp;
                bf[nf][0] = bs[row * KPAD + kb + tg];
                bf[nf][1] = bs[row * KPAD + kb + tg + 4];
            }
            #pragma unroll
            for (int mf = 0; mf < 4; mf++)
                #pragma unroll
                for (int nf = 0; nf < 4; nf++)
                    mma8(acc[mf][nf], af[mf], bf[nf]);
        }
        if (t < KT - 1) STS_TILE(buf ^ 1);
        __syncthreads();
        buf ^= 1;
    }
#undef STS_TILE

    float* Cq = (dst == 0) ? g_q : (dst == 1) ? g_k : g_v;

    #pragma unroll
    for (int mf = 0; mf < 4; mf++) {
        #pragma unroll
        for (int nf = 0; nf < 4; nf++) {
            const int n0 = bn + wn + nf * 8 + tg * 2;
            const float b0 = bias[n0], b1 = bias[n0 + 1];
            #pragma unroll
            for (int half = 0; half < 2; half++) {
                const int m = bm + wm + mf * 16 + gp + half * 8;
                const float v0 = (acc[mf][nf][half * 2 + 0] + b0) * scale;
                const float v1 = (acc[mf][nf][half * 2 + 1] + b1) * scale;
                if (dst < 3) {
                    const int b = m >> 9, s = m & 511;
                    const int h = n0 >> 6, d = n0 & 63;
                    const long base = (((long)(b * NHEAD + h)) * SEQ + s) * HD;
                    Cq[base + d]     = v0;
                    Cq[base + d + 1] = v1;
                } else {
                    Cout[(long)m * HID + n0]     = v0;
                    Cout[(long)m * HID + n0 + 1] = v1;
                }
            }
        }
    }
}

// ===========================================================================
// Plain-tf32 mma fused attention. Block = (b, h, 32-query tile). 8 warps.
// smem: sc[32][516] fp32/tf32-bits + KV[64][68] tf32  = 83,456 B -> 2 CTA/SM
// Q fragments hoisted to registers for the whole kernel; all tf32 cvts happen
// at tile-store / phase-2-write time; mma inner loops issue only LDS + mma.
// ===========================================================================
#define QT  32
#define SCP 516
#define KVP 68
#define SMEM_ATTN ((QT*SCP + 64*KVP) * (int)sizeof(float))

__global__ __launch_bounds__(256, 2)
void attn_mma(const float* __restrict__ mask, const float* __restrict__ kg,
              const int* __restrict__ lena, const float* __restrict__ hy,
              const int* __restrict__ layer_p)
{
    extern __shared__ float sm[];
    float*    sc = sm;                              // [32][516]
    unsigned* kv = (unsigned*)(sm + QT * SCP);      // [64][68] tf32

    const int tid = threadIdx.x;
    const int bh = blockIdx.x;
    const int b = bh >> 4, h = bh & 15;
    const int q0 = blockIdx.y * QT;

    const long head_off = ((long)(b * NHEAD + h)) * SEQ * HD;

    const int wid = tid >> 5, lane = tid & 31;
    const int g8 = lane >> 2;        // 0..7
    const int tg = lane & 3;         // 0..3
    const int wm = (wid >> 2) * 16;  // 0 or 16 (query rows within tile)
    const int wn = (wid & 3) * 16;   // 0,16,32,48 (cols within 64-wide kt tile)

    // KV tile loader mapping: row = tid>>2 (0..63), 16 consecutive cols
    const int lr = tid >> 2;
    const int lcb = (tid & 3) * 16;

    // ---- hoist Q fragments into registers (whole kernel lifetime) ----
    unsigned qa[8][4];
    {
        const float* q_r0 = g_q + head_off + (long)(q0 + wm + g8)     * HD;
        const float* q_r1 = g_q + head_off + (long)(q0 + wm + g8 + 8) * HD;
        #pragma unroll
        for (int kb = 0; kb < 8; kb++) {
            qa[kb][0] = f2tf(q_r0[kb * 8 + tg]);
            qa[kb][1] = f2tf(q_r1[kb * 8 + tg]);
            qa[kb][2] = f2tf(q_r0[kb * 8 + tg + 4]);
            qa[kb][3] = f2tf(q_r1[kb * 8 + tg + 4]);
        }
    }

    // ================= Phase 1: scores = Q K^T + mask =================
    {
        const float* kbase = g_k + head_off + (long)lr * HD + lcb;
        float4 pf[4];
        #pragma unroll
        for (int i = 0; i < 4; i++) pf[i] = *(const float4*)(kbase + i * 4);

        for (int kt = 0; kt < 8; kt++) {
            __syncthreads();
            #pragma unroll
            for (int i = 0; i < 4; i++) {
                unsigned* dst = kv + lr * KVP + lcb + i * 4;
                dst[0] = f2tf(pf[i].x); dst[1] = f2tf(pf[i].y);
                dst[2] = f2tf(pf[i].z); dst[3] = f2tf(pf[i].w);
            }
            __syncthreads();
            if (kt < 7) {
                const float* nb = kbase + (long)(kt + 1) * 64 * HD;
                #pragma unroll
                for (int i = 0; i < 4; i++) pf[i] = *(const float4*)(nb + i * 4);
            }

            float acc[2][4];
            #pragma unroll
            for (int nf = 0; nf < 2; nf++)
                #pragma unroll
                for (int k = 0; k < 4; k++) acc[nf][k] = 0.f;

            #pragma unroll
            for (int kb = 0; kb < 8; kb++) {
                unsigned bf[2][2];
                #pragma unroll
                for (int nf = 0; nf < 2; nf++) {
                    const unsigned* base = kv + (wn + nf * 8 + g8) * KVP + kb * 8 + tg;
                    bf[nf][0] = base[0];
                    bf[nf][1] = base[4];
                }
                #pragma unroll
                for (int nf = 0; nf < 2; nf++)
                    mma8(acc[nf], qa[kb], bf[nf]);
            }

            #pragma unroll
            for (int nf = 0; nf < 2; nf++) {
                const int c = kt * 64 + wn + nf * 8 + 2 * tg;
                #pragma unroll
                for (int half = 0; half < 2; half++) {
                    const int r = wm + g8 + half * 8;
                    const float* mrow = mask + ((long)b * SEQ + (q0 + r)) * SEQ + c;
                    sc[r * SCP + c]     = acc[nf][half * 2 + 0] + mrow[0];
                    sc[r * SCP + c + 1] = acc[nf][half * 2 + 1] + mrow[1];
                }
            }
        }
    }
    __syncthreads();

    // ================= Phase 2: softmax + probs mods (write tf32 bits) =====
    {
        const int l  = lena[b];
        const int ly = *layer_p;
        const float ha = hy[ly * 3 + 0];
        const float hb = hy[ly * 3 + 1];
        const float hc = hy[ly * 3 + 2];
        const float* simp = kg + (long)b * 2 * SEQ * SEQ;
        const float* topp = simp + (long)SEQ * SEQ;

        for (int r = wid; r < QT; r += 8) {
            float* row = sc + r * SCP;
            const int qg = q0 + r;

            float mx = -1e30f;
            #pragma unroll 4
            for (int j = lane; j < SEQ; j += 32) mx = fmaxf(mx, row[j]);
            #pragma unroll
            for (int o = 16; o > 0; o >>= 1) mx = fmaxf(mx, __shfl_xor_sync(0xffffffffu, mx, o));

            float s = 0.f;
            #pragma unroll 4
            for (int j = lane; j < SEQ; j += 32) {
                float e = __expf(row[j] - mx);
                row[j] = e;
                s += e;
            }
            #pragma unroll
            for (int o = 16; o > 0; o >>= 1) s += __shfl_xor_sync(0xffffffffu, s, o);
            const float inv = 1.0f / s;

            const bool ra_q = (qg >= 1) && (qg < l - 1);
            const bool ca_q = (qg >= l) && (qg < SEQ - 1);
            const long krow = (long)qg * SEQ;
            #pragma unroll 4
            for (int j = lane; j < SEQ; j += 32) {
                const bool ra_j = (j >= 1) && (j < l - 1);
                const bool ca_j = (j >= l) && (j < SEQ - 1);
                const float lg = ((ra_q && ca_j) || (ra_j && ca_q)) ? hc : 1.0f;
                const float p = row[j] * inv * lg + ha * simp[krow + j] + hb * topp[krow + j];
                row[j] = __uint_as_float(f2tf(p));   // store as tf32 bits
            }
        }
    }

    // ================= Phase 3: out = P V =================
    {
        float oacc[2][4];
        #pragma unroll
        for (int nf = 0; nf < 2; nf++)
            #pragma unroll
            for (int k = 0; k < 4; k++) oacc[nf][k] = 0.f;

        const float* vbase = g_v + head_off + (long)lr * HD + lcb;
        float4 pf[4];
        #pragma unroll
        for (int i = 0; i < 4; i++) pf[i] = *(const float4*)(vbase + i * 4);

        for (int kt = 0; kt < 8; kt++) {
            __syncthreads();
            #pragma unroll
            for (int i = 0; i < 4; i++) {
                unsigned* dst = kv + lr * KVP + lcb + i * 4;
                dst[0] = f2tf(pf[i].x); dst[1] = f2tf(pf[i].y);
                dst[2] = f2tf(pf[i].z); dst[3] = f2tf(pf[i].w);
            }
            __syncthreads();
            if (kt < 7) {
                const float* nb = vbase + (long)(kt + 1) * 64 * HD;
                #pragma unroll
                for (int i = 0; i < 4; i++) pf[i] = *(const float4*)(nb + i * 4);
            }

            #pragma unroll
            for (int kb = 0; kb < 8; kb++) {
                unsigned af[4], bf[2][2];
                {
                    const float* base = sc + (wm + g8) * SCP + kt * 64 + kb * 8 + tg;
                    af[0] = __float_as_uint(base[0]);
                    af[1] = __float_as_uint(base[8 * SCP]);
                    af[2] = __float_as_uint(base[4]);
                    af[3] = __float_as_uint(base[8 * SCP + 4]);
                }
                #pragma unroll
                for (int nf = 0; nf < 2; nf++) {
                    const unsigned* base = kv + (kb * 8 + tg) * KVP + wn + nf * 8 + g8;
                    bf[nf][0] = base[0];
                    bf[nf][1] = base[4 * KVP];
                }
                #pragma unroll
                for (int nf = 0; nf < 2; nf++)
                    mma8(oacc[nf], af, bf[nf]);
            }
        }

        // epilogue: write O tile to g_attn [B,S,H]
        #pragma unroll
        for (int nf = 0; nf < 2; nf++) {
            const int d0 = wn + nf * 8 + 2 * tg;
            #pragma unroll
            for (int half = 0; half < 2; half++) {
                const int r = q0 + wm + g8 + half * 8;
                float* dst = g_attn + ((long)b * SEQ + r) * HID + h * HD + d0;
                dst[0] = oacc[nf][half * 2 + 0];
                dst[1] = oacc[nf][half * 2 + 1];
            }
        }
    }
}

// ===========================================================================
extern "C" void kernel_launch(void* const* d_in, const int* in_sizes, int n_in,
                              void* d_out, int out_size)
{
    const float* query = (const float*)d_in[0];
    const float* key   = (const float*)d_in[1];
    const float* value = (const float*)d_in[2];
    const float* mask  = (const float*)d_in[3];
    const int*   lena  = (const int*)  d_in[4];
    const float* kg    = (const float*)d_in[5];
    const float* hy    = (const float*)d_in[6];
    const int*   layer = (const int*)  d_in[7];
    const float* Wq    = (const float*)d_in[8];
    const float* bq    = (const float*)d_in[9];
    const float* Wk    = (const float*)d_in[10];
    const float* bk    = (const float*)d_in[11];
    const float* Wv    = (const float*)d_in[12];
    const float* bv    = (const float*)d_in[13];
    const float* Wo    = (const float*)d_in[14];
    const float* bo    = (const float*)d_in[15];
    float* out = (float*)d_out;

    static int smem_set = 0;
    if (!smem_set) {
        cudaFuncSetAttribute(attn_mma,
                             cudaFuncAttributeMaxDynamicSharedMemorySize, SMEM_ATTN);
        smem_set = 1;
    }

    const dim3 ggrid(HID / 128, MROWS / 128);   // (8, 32)
    const float qscale = 0.125f;                // 1/sqrt(64)

    gemm_tf32<<<ggrid, 256>>>(query, Wq, bq, nullptr, qscale, 0);
    gemm_tf32<<<ggrid, 256>>>(key,   Wk, bk, nullptr, 1.0f,   1);
    gemm_tf32<<<ggrid, 256>>>(value, Wv, bv, nullptr, 1.0f,   2);

    dim3 attn_grid(BATCH * NHEAD, SEQ / QT);    // (128, 16)
    attn_mma<<<attn_grid, 256, SMEM_ATTN>>>(mask, kg, lena, hy, layer);

    gemm_tf32<<<ggrid, 256>>>(nullptr, Wo, bo, out, 1.0f, 3);
}